// round 3
// baseline (speedup 1.0000x reference)
#include <cuda_runtime.h>
#include <cuda_fp16.h>

// Problem constants: N_UNIQUE=10000, N_BASES=10, FILTERS=16, B=32, L=100000
#define N_UNIQUE 10000
#define N_BASES  10
#define FILTERS  16
#define N_ELEMS  (32 * 100000)           // 3,200,000
#define N_OUT4   (N_ELEMS * 4)           // 12,800,000 float4 outputs
#define UNROLL   4
#define TPB      256
#define GATHER_BLOCKS (N_OUT4 / (TPB * UNROLL))   // 12500 exactly, no tail

// Precomputed unique-value table in FP16 (no bias — bias added in fp32 at
// gather time to keep quantization error limited to the matmul result).
// Row u = 16 halves = 32 bytes = ONE L2 sector (fp32 was two).
__device__ __half g_tab[N_UNIQUE * FILTERS];

// Kernel 1: tab[u][f] = (half) sum_b X_spline[u][b] * kernel[b][f]
__global__ void precompute_shrunk(const float* __restrict__ X_spline,
                                  const float* __restrict__ kern) {
    int t = blockIdx.x * blockDim.x + threadIdx.x;
    if (t >= N_UNIQUE * FILTERS) return;
    int u = t >> 4;
    int f = t & 15;
    float acc = 0.f;
#pragma unroll
    for (int b = 0; b < N_BASES; ++b)
        acc = fmaf(__ldg(X_spline + u * N_BASES + b), __ldg(kern + b * FILTERS + f), acc);
    g_tab[t] = __float2half_rn(acc);
}

// Kernel 2: out[e][f] = (float)tab[idx[e]][f] + bias[f]
// Thread -> float4 slot i: element e=i>>2, quarter j=i&3 (j constant per
// thread). Gather reads 8B of halves per lane (4 lanes = 32B = 1 sector per
// random row). Stores are coalesced fp32 float4, streaming.
__global__ __launch_bounds__(TPB) void gather_out(const int* __restrict__ idx,
                                                  const float4* __restrict__ bias4,
                                                  float4* __restrict__ out4) {
    const unsigned base = blockIdx.x * (TPB * UNROLL) + threadIdx.x;
    const unsigned j = threadIdx.x & 3u;           // quarter, fixed per thread
    const float4 bj = __ldg(bias4 + j);            // bias[4j..4j+3] in regs

    // Phase 1: independent idx loads (streamed).
    int u[UNROLL];
#pragma unroll
    for (int k = 0; k < UNROLL; ++k)
        u[k] = __ldcs(idx + ((base + k * TPB) >> 2));

    // Phase 2: independent fp16 table gathers (8B per lane, L2-resident).
    uint2 h[UNROLL];
#pragma unroll
    for (int k = 0; k < UNROLL; ++k)
        h[k] = __ldg((const uint2*)(g_tab + (unsigned)u[k] * 16u) + j);

    // Phase 3: convert + bias in fp32, streaming stores.
#pragma unroll
    for (int k = 0; k < UNROLL; ++k) {
        float2 lo = __half22float2(*reinterpret_cast<__half2*>(&h[k].x));
        float2 hi = __half22float2(*reinterpret_cast<__half2*>(&h[k].y));
        float4 v;
        v.x = lo.x + bj.x;
        v.y = lo.y + bj.y;
        v.z = hi.x + bj.z;
        v.w = hi.y + bj.w;
        __stcs(out4 + (base + k * TPB), v);
    }
}

extern "C" void kernel_launch(void* const* d_in, const int* in_sizes, int n_in,
                              void* d_out, int out_size) {
    // Identify inputs by element count (all distinct):
    // idx: 3,200,000 | X_spline: 100,000 | kernel: 160 | bias: 16
    const int*   idx      = nullptr;
    const float* X_spline = nullptr;
    const float* kern     = nullptr;
    const float* bias     = nullptr;
    for (int i = 0; i < n_in; ++i) {
        switch (in_sizes[i]) {
            case N_ELEMS:             idx      = (const int*)  d_in[i]; break;
            case N_UNIQUE * N_BASES:  X_spline = (const float*)d_in[i]; break;
            case N_BASES * FILTERS:   kern     = (const float*)d_in[i]; break;
            case FILTERS:             bias     = (const float*)d_in[i]; break;
            default: break;
        }
    }

    {
        int total = N_UNIQUE * FILTERS;
        precompute_shrunk<<<(total + TPB - 1) / TPB, TPB>>>(X_spline, kern);
    }
    gather_out<<<GATHER_BLOCKS, TPB>>>(idx, (const float4*)bias, (float4*)d_out);
}

// round 4
// speedup vs baseline: 1.3908x; 1.3908x over previous
#include <cuda_runtime.h>

// Problem constants: N_UNIQUE=10000, N_BASES=10, FILTERS=16, B=32, L=100000
#define N_UNIQUE 10000
#define N_BASES  10
#define FILTERS  16
#define N_ELEMS  (32 * 100000)           // 3,200,000
#define N_OUT4   (N_ELEMS * 4)           // 12,800,000 float4 outputs
#define UNROLL   8
#define TPB      256
// 12,800,000 / (256*8) = 6250 exactly — no tail predicate needed.
#define GATHER_BLOCKS (N_OUT4 / (TPB * UNROLL))

// Precomputed bias-fused unique-value table, fp32 (device global scratch).
__device__ float4 g_shrunk4[N_UNIQUE * 4];   // [n_unique][16 floats] as 4x float4

// Kernel 1: shrunk_biased[u][f] = sum_b X_spline[u][b]*kernel[b][f] + bias[f]
__global__ void precompute_shrunk(const float* __restrict__ X_spline,
                                  const float* __restrict__ kern,
                                  const float* __restrict__ bias) {
    int t = blockIdx.x * blockDim.x + threadIdx.x;
    if (t >= N_UNIQUE * FILTERS) return;
    int u = t >> 4;
    int f = t & 15;
    float acc = __ldg(bias + f);
#pragma unroll
    for (int b = 0; b < N_BASES; ++b)
        acc = fmaf(__ldg(X_spline + u * N_BASES + b), __ldg(kern + b * FILTERS + f), acc);
    reinterpret_cast<float*>(g_shrunk4)[t] = acc;
}

// Kernel 2: out[e][f] = table[idx[e]][f], 8 independent chains per thread.
// float4 slot i -> element e=i>>2, quarter j=i&3: every load/store is fully
// coalesced across the warp; table row read cooperatively by 4 lanes (16B ea).
__global__ __launch_bounds__(TPB) void gather_out(const int* __restrict__ idx,
                                                  float4* __restrict__ out4) {
    const unsigned base = blockIdx.x * (TPB * UNROLL) + threadIdx.x;

    // Phase 1: 8 independent idx loads (streamed — read exactly once).
    int u[UNROLL];
#pragma unroll
    for (int k = 0; k < UNROLL; ++k)
        u[k] = __ldcs(idx + ((base + k * TPB) >> 2));

    // Phase 2: 8 independent table gathers (L2-resident, keep cached).
    float4 v[UNROLL];
#pragma unroll
    for (int k = 0; k < UNROLL; ++k) {
        unsigned i = base + k * TPB;
        v[k] = __ldg(&g_shrunk4[(unsigned)u[k] * 4u + (i & 3u)]);
    }

    // Phase 3: 8 streaming stores (write-once, evict-first).
#pragma unroll
    for (int k = 0; k < UNROLL; ++k)
        __stcs(out4 + (base + k * TPB), v[k]);
}

extern "C" void kernel_launch(void* const* d_in, const int* in_sizes, int n_in,
                              void* d_out, int out_size) {
    // Identify inputs by element count (all distinct):
    // idx: 3,200,000 | X_spline: 100,000 | kernel: 160 | bias: 16
    const int*   idx      = nullptr;
    const float* X_spline = nullptr;
    const float* kern     = nullptr;
    const float* bias     = nullptr;
    for (int i = 0; i < n_in; ++i) {
        switch (in_sizes[i]) {
            case N_ELEMS:             idx      = (const int*)  d_in[i]; break;
            case N_UNIQUE * N_BASES:  X_spline = (const float*)d_in[i]; break;
            case N_BASES * FILTERS:   kern     = (const float*)d_in[i]; break;
            case FILTERS:             bias     = (const float*)d_in[i]; break;
            default: break;
        }
    }

    {
        int total = N_UNIQUE * FILTERS;
        precompute_shrunk<<<(total + TPB - 1) / TPB, TPB>>>(X_spline, kern, bias);
    }
    gather_out<<<GATHER_BLOCKS, TPB>>>(idx, (float4*)d_out);
}

// round 6
// speedup vs baseline: 1.4444x; 1.0386x over previous
#include <cuda_runtime.h>

// Problem constants: N_UNIQUE=10000, N_BASES=10, FILTERS=16, B=32, L=100000
#define N_UNIQUE 10000
#define N_BASES  10
#define FILTERS  16
#define N_ELEMS  (32 * 100000)           // 3,200,000
#define N_OUT4   (N_ELEMS * 4)           // 12,800,000 float4 outputs
#define UNROLL   4
#define TPB      256
// 12,800,000 / (256*4) = 12500 exactly — no tail predicate.
#define GATHER_BLOCKS (N_OUT4 / (TPB * UNROLL))

// Precomputed bias-fused unique-value table, fp32 (device global scratch).
__device__ float4 g_shrunk4[N_UNIQUE * 4];   // [n_unique][16 floats] as 4x float4

// L2 evict-last policy (created once per thread): pins the hot 640KB table in
// L2 so the 205MB of streaming output writes can't thrash it out.
static __device__ __forceinline__ unsigned long long mk_evict_last_policy() {
    unsigned long long pol;
    asm("createpolicy.fractional.L2::evict_last.b64 %0, 1.0;" : "=l"(pol));
    return pol;
}

// 16B table gather with the evict-last cache hint (legal encoding on sm_103:
// immediate .L2::evict_last only allows v8.b32/v4.b64, cache_hint allows v4.f32).
static __device__ __forceinline__ float4 ldg_evict_last(const float4* p,
                                                        unsigned long long pol) {
    float4 v;
    asm volatile("ld.global.nc.L2::cache_hint.v4.f32 {%0,%1,%2,%3}, [%4], %5;"
                 : "=f"(v.x), "=f"(v.y), "=f"(v.z), "=f"(v.w)
                 : "l"(p), "l"(pol));
    return v;
}

// Kernel 1: shrunk_biased[u][f] = sum_b X_spline[u][b]*kernel[b][f] + bias[f]
__global__ void precompute_shrunk(const float* __restrict__ X_spline,
                                  const float* __restrict__ kern,
                                  const float* __restrict__ bias) {
    int t = blockIdx.x * blockDim.x + threadIdx.x;
    if (t >= N_UNIQUE * FILTERS) return;
    int u = t >> 4;
    int f = t & 15;
    float acc = __ldg(bias + f);
#pragma unroll
    for (int b = 0; b < N_BASES; ++b)
        acc = fmaf(__ldg(X_spline + u * N_BASES + b), __ldg(kern + b * FILTERS + f), acc);
    reinterpret_cast<float*>(g_shrunk4)[t] = acc;
}

// Kernel 2: out[e][f] = table[idx[e]][f], 4 independent chains per thread.
// float4 slot i -> element e=i>>2, quarter j=i&3: all loads/stores fully
// coalesced; each random 64B table row read cooperatively by 4 lanes.
__global__ __launch_bounds__(TPB) void gather_out(const int* __restrict__ idx,
                                                  float4* __restrict__ out4) {
    const unsigned base = blockIdx.x * (TPB * UNROLL) + threadIdx.x;
    const unsigned long long pol = mk_evict_last_policy();

    // Phase 1: 4 independent idx loads (streaming — read exactly once).
    int u[UNROLL];
#pragma unroll
    for (int k = 0; k < UNROLL; ++k)
        u[k] = __ldcs(idx + ((base + k * TPB) >> 2));

    // Phase 2: 4 independent table gathers, L2 evict-last (table stays hot).
    float4 v[UNROLL];
#pragma unroll
    for (int k = 0; k < UNROLL; ++k) {
        unsigned i = base + k * TPB;
        v[k] = ldg_evict_last(&g_shrunk4[(unsigned)u[k] * 4u + (i & 3u)], pol);
    }

    // Phase 3: 4 streaming stores (write-once, evict-first in L1 and L2).
#pragma unroll
    for (int k = 0; k < UNROLL; ++k)
        __stcs(out4 + (base + k * TPB), v[k]);
}

extern "C" void kernel_launch(void* const* d_in, const int* in_sizes, int n_in,
                              void* d_out, int out_size) {
    // Identify inputs by element count (all distinct):
    // idx: 3,200,000 | X_spline: 100,000 | kernel: 160 | bias: 16
    const int*   idx      = nullptr;
    const float* X_spline = nullptr;
    const float* kern     = nullptr;
    const float* bias     = nullptr;
    for (int i = 0; i < n_in; ++i) {
        switch (in_sizes[i]) {
            case N_ELEMS:             idx      = (const int*)  d_in[i]; break;
            case N_UNIQUE * N_BASES:  X_spline = (const float*)d_in[i]; break;
            case N_BASES * FILTERS:   kern     = (const float*)d_in[i]; break;
            case FILTERS:             bias     = (const float*)d_in[i]; break;
            default: break;
        }
    }

    {
        int total = N_UNIQUE * FILTERS;
        precompute_shrunk<<<(total + TPB - 1) / TPB, TPB>>>(X_spline, kern, bias);
    }
    gather_out<<<GATHER_BLOCKS, TPB>>>(idx, (float4*)d_out);
}